// round 4
// baseline (speedup 1.0000x reference)
#include <cuda_runtime.h>
#include <math.h>

// ---------------------------------------------------------------------------
// casConv2d: B=1, C=128, H=W=32, OC=128, K=3, pad=1 -> OH=OW=32, L=1024
// ckk = 1152, ARRAY_SIZE=32 -> reference's front-pad chunk is all-zero
// (contributes exactly 0 after fake-quant), leaving 36 real chunks:
//   chunk j (0..35) = ckk indices [32j, 32j+32), idx = c*9 + kh*3 + kw
//
// Kernel 1: per-chunk partial sums -> g_part[l][j][oc]   (fp32, 18.9 MB, L2)
// Kernel 2: two-pass: totals(+bias) -> scale/zp (warp=one l) -> fake-quant
//           re-reading partials from L1/L2 -> out[oc][l]
// ---------------------------------------------------------------------------

#define WSTR 130  // w_s row stride (floats)

typedef unsigned long long u64;

__device__ float g_part[1024u * 36u * 128u];  // [l][j][oc]

__device__ __forceinline__ u64 fma2(u64 a, u64 b, u64 c) {
    u64 d;
    asm("fma.rn.f32x2 %0, %1, %2, %3;" : "=l"(d) : "l"(a), "l"(b), "l"(c));
    return d;
}

__device__ __forceinline__ u64 bcast2(float v) {
    u64 d;
    unsigned u = __float_as_uint(v);
    asm("mov.b64 %0, {%1, %1};" : "=l"(d) : "r"(u));
    return d;
}

__device__ __forceinline__ float2 unpack2(u64 v) {
    float2 f;
    asm("mov.b64 {%0, %1}, %2;" : "=f"(f.x), "=f"(f.y) : "l"(v));
    return f;
}

// ---------------------------------------------------------------------------
// Kernel 1: chunk partial sums.
// grid = (16 l-tiles, 36 chunks), block = 256 threads.
// Block tile: 128 oc x 64 l (2 output rows x 32 cols).
// Thread tile: 8 oc x 4 l = 4 oc-pair f32x2 accumulators x 4 l (32 regs).
// Per-t smem offset table kills the div/mod address math.
// ---------------------------------------------------------------------------
__global__ void __launch_bounds__(256)
k_partials(const float* __restrict__ x, const float* __restrict__ w) {
    __shared__ float x_s[5 * 4 * 34];     // [c_rel][row(4)][col(34)], zero halo
    __shared__ float w_s[32 * WSTR];      // [t][oc], padded stride
    __shared__ int   xoff_s[32];          // per-t base offset into x_s

    const int j    = blockIdx.y;
    const int oh0  = blockIdx.x * 2;      // first output row of this tile
    const int base = 32 * j;              // first ckk index of this chunk
    const int cmin = base / 9;            // first channel touched (<=5 channels)
    const int r0   = base - 9 * cmin;     // base % 9
    const int tid  = threadIdx.x;

    // --- per-t offset table: idx9 = r0 + t; off = c_rel*136 + kh*34 + kw
    if (tid < 32) {
        int idx9 = r0 + tid;
        int cr   = idx9 / 9;
        int rem  = idx9 - cr * 9;
        int kh   = rem / 3;
        int kw   = rem - kh * 3;
        xoff_s[tid] = cr * 136 + kh * 34 + kw;
    }

    // --- load x halo: channels cmin..cmin+4, rows oh0-1..oh0+2, cols -1..32
    for (int e = tid; e < 5 * 4 * 34; e += 256) {
        int cr  = e / 136;
        int rem = e - cr * 136;
        int rr  = rem / 34;
        int cc  = rem - rr * 34;
        int c   = cmin + cr;
        int gh  = oh0 - 1 + rr;
        int gw  = cc - 1;
        float v = 0.0f;
        if (c < 128 && (unsigned)gh < 32u && (unsigned)gw < 32u)
            v = x[(c << 10) + (gh << 5) + gw];
        x_s[e] = v;
    }
    // --- load w: w_s[m][oc] = w[oc*1152 + base + m]  (coalesced global reads)
    for (int e = tid; e < 4096; e += 256) {
        int oc = e >> 5;
        int m  = e & 31;
        w_s[m * WSTR + oc] = w[oc * 1152 + base + m];
    }
    __syncthreads();

    const int lcol = tid & 15;            // 16 l-groups of 4
    const int oc0  = (tid >> 4) << 3;     // 16 oc-groups of 8
    const int lrow = lcol >> 3;           // output row within tile (0..1)
    const int colb = (lcol & 7) << 2;     // first output col (0,4,...,28)
    const int xrowoff = lrow * 34 + colb;

    u64 acc[4][4];                        // [oc-pair][l] f32x2 accumulators
#pragma unroll
    for (int p = 0; p < 4; ++p)
#pragma unroll
        for (int i = 0; i < 4; ++i) acc[p][i] = 0ull;

#pragma unroll
    for (int t = 0; t < 32; ++t) {
        const float* xr = &x_s[xoff_s[t] + xrowoff];
        const u64*   wr = (const u64*)&w_s[t * WSTR + oc0];
        const u64 w0 = wr[0], w1 = wr[1], w2 = wr[2], w3 = wr[3];
#pragma unroll
        for (int i = 0; i < 4; ++i) {
            const u64 xx = bcast2(xr[i]);
            acc[0][i] = fma2(w0, xx, acc[0][i]);
            acc[1][i] = fma2(w1, xx, acc[1][i]);
            acc[2][i] = fma2(w2, xx, acc[2][i]);
            acc[3][i] = fma2(w3, xx, acc[3][i]);
        }
    }

    // --- store partials: g_part[l][j][oc], l = (oh0+lrow)*32 + colb + i
    const int lbase = (oh0 + lrow) * 32 + colb;
    float* outp = g_part + (size_t)(j << 7) + oc0;
#pragma unroll
    for (int i = 0; i < 4; ++i) {
        float2 a0 = unpack2(acc[0][i]);
        float2 a1 = unpack2(acc[1][i]);
        float2 a2 = unpack2(acc[2][i]);
        float2 a3 = unpack2(acc[3][i]);
        float* po = outp + (size_t)(lbase + i) * 4608;
        *(float4*)(po)     = make_float4(a0.x, a0.y, a1.x, a1.y);
        *(float4*)(po + 4) = make_float4(a2.x, a2.y, a3.x, a3.y);
    }
}

// ---------------------------------------------------------------------------
// Kernel 2: two-pass fused reduce/quant. grid=128, block=256 (8 warps).
// One warp per l; lane holds 4 consecutive oc as float4 (LDG.128 streams).
// Pass 1: totals -> warp max/min -> scale/zp. Pass 2: re-read (L1/L2) -> quant.
// Unroll capped to keep regs ~48 and occupancy high.
// ---------------------------------------------------------------------------
__global__ void __launch_bounds__(256)
k_quant(const float* __restrict__ bias, float* __restrict__ out) {
    const int tid  = threadIdx.x;
    const int lane = tid & 31;
    const int wid  = tid >> 5;
    const int l    = (blockIdx.x << 3) + wid;
    const int oc0  = lane << 2;

    const float4* bp = (const float4*)(g_part + (size_t)l * 4608) + lane;
    // j stride in float4 units: 128/4 = 32

    // --- pass 1: totals (+bias)
    float4 t4 = *(const float4*)(bias + oc0);
#pragma unroll 4
    for (int j = 0; j < 36; ++j) {
        float4 v = bp[j * 32];
        t4.x += v.x; t4.y += v.y; t4.z += v.z; t4.w += v.w;
    }
    float mx = fmaxf(fmaxf(t4.x, t4.y), fmaxf(t4.z, t4.w));
    float mn = fminf(fminf(t4.x, t4.y), fminf(t4.z, t4.w));
#pragma unroll
    for (int s = 16; s > 0; s >>= 1) {
        mx = fmaxf(mx, __shfl_xor_sync(0xffffffffu, mx, s));
        mn = fminf(mn, __shfl_xor_sync(0xffffffffu, mn, s));
    }

    const float sc = (mx - mn) * (1.0f / 255.0f);
    float z = -mn / sc;                              // inf/nan if sc==0
    z = fminf(fmaxf(z, 0.0f), 255.0f);               // clip (nan -> 0 via fmaxf)
    if (isnan(z)) z = 0.0f;
    const float zp  = truncf(z);                     // .int() truncation
    const float rcp = 1.0f / sc;

    // --- pass 2: fake-quant each chunk, sum (q - zp) exactly (small ints)
    float4 o = make_float4(0.f, 0.f, 0.f, 0.f);
#pragma unroll 4
    for (int j = 0; j < 36; ++j) {
        float4 v = bp[j * 32];
        float qx = fminf(fmaxf(rintf(v.x * rcp) + zp, 0.0f), 255.0f);
        float qy = fminf(fmaxf(rintf(v.y * rcp) + zp, 0.0f), 255.0f);
        float qz = fminf(fmaxf(rintf(v.z * rcp) + zp, 0.0f), 255.0f);
        float qw = fminf(fmaxf(rintf(v.w * rcp) + zp, 0.0f), 255.0f);
        o.x += qx - zp; o.y += qy - zp; o.z += qz - zp; o.w += qw - zp;
    }
    o.x *= sc; o.y *= sc; o.z *= sc; o.w *= sc;

    // --- transpose through smem for coalesced [oc][l] stores
    __shared__ float s[8 * 132];                     // [wid][oc], padded
    *(float4*)(s + wid * 132 + oc0) = o;
    __syncthreads();
    const int l0 = blockIdx.x << 3;
    for (int e = tid; e < 1024; e += 256) {
        int oc = e >> 3, c = e & 7;
        out[(oc << 10) + l0 + c] = s[c * 132 + oc];
    }
}

// ---------------------------------------------------------------------------
extern "C" void kernel_launch(void* const* d_in, const int* in_sizes, int n_in,
                              void* d_out, int out_size) {
    const float *x = nullptr, *w = nullptr, *b = nullptr;
    for (int i = 0; i < n_in; ++i) {
        if      (in_sizes[i] == 131072) x = (const float*)d_in[i];  // 128*32*32
        else if (in_sizes[i] == 147456) w = (const float*)d_in[i];  // 128*128*9
        else if (in_sizes[i] == 128)    b = (const float*)d_in[i];
    }
    k_partials<<<dim3(16, 36), 256>>>(x, w);
    k_quant<<<128, 256>>>(b, (float*)d_out);
}